// round 17
// baseline (speedup 1.0000x reference)
#include <cuda_runtime.h>

#define N_USER   200000
#define N_ITEM   100000
#define N_NODES_ 300000
#define EMB      80
#define EMBV     20          // float4 chunks per row
#define FEAT     16
#define NNZ_     1000000
#define BATCH_   4096
#define NSEL     (3 * BATCH_)   // 12288 selected rows
#define NLAYER   3

// ---------------- device scratch ----------------
static __device__ float  g_E [(size_t)N_NODES_ * EMB];   // 96 MB
static __device__ float  g_LE[(size_t)N_NODES_ * EMB];   // 96 MB
static __device__ float  g_LEsel[(size_t)NSEL * EMB];
static __device__ float  g_Esel [(size_t)NSEL * EMB];
static __device__ float2 g_Whl[NLAYER * 160 * EMB];      // per-layer [k:160][n:80] (hi,lo)
static __device__ int    g_nodes[NSEL];
static __device__ int    g_rowptr[N_NODES_ + 1];
static __device__ int    g_cnt[N_NODES_];
static __device__ int    g_bsum[1024];
static __device__ int    g_winner[N_USER];
static __device__ int    g_cols[NNZ_];
static __device__ float  g_vals[NNZ_];
// frontier sets
static __device__ int    g_flag1[N_NODES_];
static __device__ int    g_flag2[N_NODES_];
static __device__ int    g_list1[N_NODES_];
static __device__ int    g_list2[N_NODES_];
static __device__ int    g_n1;
static __device__ int    g_n2;

// ---------------- tf32 helpers ----------------
__device__ __forceinline__ unsigned tf32_of(float x) {
    unsigned r;
    asm("cvt.rna.tf32.f32 %0, %1;" : "=r"(r) : "f"(x));
    return r;
}

__device__ __forceinline__ void mma_tf32(float c[4],
                                         unsigned a0, unsigned a1, unsigned a2, unsigned a3,
                                         unsigned b0, unsigned b1) {
    asm volatile("mma.sync.aligned.m16n8k8.row.col.f32.tf32.tf32.f32 "
                 "{%0,%1,%2,%3}, {%4,%5,%6,%7}, {%8,%9}, {%0,%1,%2,%3};"
                 : "+f"(c[0]), "+f"(c[1]), "+f"(c[2]), "+f"(c[3])
                 : "r"(a0), "r"(a1), "r"(a2), "r"(a3), "r"(b0), "r"(b1));
}

// ---------------- CSR build ----------------
__global__ void k_init() {
    int i = blockIdx.x * blockDim.x + threadIdx.x;
    if (i < N_NODES_) {
        g_cnt[i]   = 0;
        g_flag1[i] = 0;
        g_flag2[i] = 0;
    }
    if (i < N_USER) g_winner[i] = -1;
    if (i == 0) { g_n1 = 0; g_n2 = 0; }
}

__global__ void k_hist(const int* __restrict__ rows) {
    int i = blockIdx.x * blockDim.x + threadIdx.x;
    if (i < NNZ_) atomicAdd(&g_cnt[rows[i]], 1);
}

__global__ void k_scan1() {
    __shared__ int s[1024];
    int tid = threadIdx.x;
    int i = blockIdx.x * 1024 + tid;
    int v = (i < N_NODES_) ? g_cnt[i] : 0;
    s[tid] = v; __syncthreads();
    for (int off = 1; off < 1024; off <<= 1) {
        int t = (tid >= off) ? s[tid - off] : 0;
        __syncthreads();
        s[tid] += t;
        __syncthreads();
    }
    if (i < N_NODES_) g_rowptr[i] = s[tid] - v;
    if (tid == 1023) g_bsum[blockIdx.x] = s[1023];
}

__global__ void k_scan2(int nb) {
    __shared__ int s[1024];
    int tid = threadIdx.x;
    int v = (tid < nb) ? g_bsum[tid] : 0;
    s[tid] = v; __syncthreads();
    for (int off = 1; off < 1024; off <<= 1) {
        int t = (tid >= off) ? s[tid - off] : 0;
        __syncthreads();
        s[tid] += t;
        __syncthreads();
    }
    if (tid < nb) g_bsum[tid] = s[tid] - v;
}

__global__ void k_scan3() {
    int i = blockIdx.x * blockDim.x + threadIdx.x;
    if (i < N_NODES_) {
        int excl = g_rowptr[i] + g_bsum[i >> 10];
        g_rowptr[i] = excl;
        g_cnt[i]    = excl;
    }
    if (i == 0) g_rowptr[N_NODES_] = NNZ_;
}

__global__ void k_scatter(const int* __restrict__ rows, const int* __restrict__ cols,
                          const float* __restrict__ vals) {
    int i = blockIdx.x * blockDim.x + threadIdx.x;
    if (i < NNZ_) {
        int p = atomicAdd(&g_cnt[rows[i]], 1);
        g_cols[p] = cols[i];
        g_vals[p] = vals[i];
    }
}

// ---------------- W split precompute (hi/lo tf32 pairs, [W1;W2] concat) ----------------
__global__ void k_wsplit(const float* __restrict__ W1, const float* __restrict__ W2) {
    int idx = blockIdx.x * blockDim.x + threadIdx.x;
    if (idx >= NLAYER * 160 * EMB) return;
    int l = idx / (160 * EMB);
    int r = idx % (160 * EMB);
    int k = r / EMB;
    int n = r % EMB;
    float w = (k < EMB) ? W1[((size_t)l * EMB + k) * EMB + n]
                        : W2[((size_t)l * EMB + (k - EMB)) * EMB + n];
    unsigned hb = tf32_of(w);
    float hi = __uint_as_float(hb);
    float lo = __uint_as_float(tf32_of(w - hi));
    g_Whl[idx] = make_float2(hi, lo);
}

// ---------------- E init + blend scatter + node list ----------------
__global__ void k_init_E(const float4* __restrict__ user_tab, const float4* __restrict__ item_tab) {
    int i = blockIdx.x * blockDim.x + threadIdx.x;
    const int tot_u = N_USER * EMBV;
    const int tot   = N_NODES_ * EMBV;
    if (i < tot_u)      ((float4*)g_E)[i] = user_tab[i];
    else if (i < tot)   ((float4*)g_E)[i] = item_tab[i - tot_u];
}

__global__ void k_winner(const int* __restrict__ u_id) {
    int i = blockIdx.x * blockDim.x + threadIdx.x;
    if (i < BATCH_) atomicMax(&g_winner[u_id[i]], i);
}

__global__ void k_blend(const int* __restrict__ u_id, const int* __restrict__ age,
                        const int* __restrict__ sex, const int* __restrict__ month,
                        const int* __restrict__ day, const int* __restrict__ dow,
                        const float* __restrict__ user_tab,
                        const float* __restrict__ age_tab, const float* __restrict__ sex_tab,
                        const float* __restrict__ month_tab, const float* __restrict__ day_tab,
                        const float* __restrict__ dow_tab) {
    int i = blockIdx.x * blockDim.x + threadIdx.x;
    if (i >= BATCH_) return;
    int u = u_id[i];
    if (g_winner[u] != i) return;   // last occurrence wins
    float*       dst = g_E + (size_t)u * EMB;
    const float* src = user_tab + (size_t)u * EMB;
    const float* t0 = age_tab   + age[i]   * FEAT;
    const float* t1 = sex_tab   + sex[i]   * FEAT;
    const float* t2 = month_tab + month[i] * FEAT;
    const float* t3 = day_tab   + day[i]   * FEAT;
    const float* t4 = dow_tab   + dow[i]   * FEAT;
    #pragma unroll
    for (int j = 0; j < FEAT; j++) {
        dst[0*FEAT+j] = 0.5f * (src[0*FEAT+j] + t0[j]);
        dst[1*FEAT+j] = 0.5f * (src[1*FEAT+j] + t1[j]);
        dst[2*FEAT+j] = 0.5f * (src[2*FEAT+j] + t2[j]);
        dst[3*FEAT+j] = 0.5f * (src[3*FEAT+j] + t3[j]);
        dst[4*FEAT+j] = 0.5f * (src[4*FEAT+j] + t4[j]);
    }
}

__global__ void k_nodes(const int* __restrict__ u_id, const int* __restrict__ pos,
                        const int* __restrict__ neg) {
    int i = blockIdx.x * blockDim.x + threadIdx.x;
    if (i >= NSEL) return;
    int node;
    if (i < BATCH_)          node = u_id[i];
    else if (i < 2 * BATCH_) node = N_USER + pos[i - BATCH_];
    else                     node = N_USER + neg[i - 2 * BATCH_];
    g_nodes[i] = node;
}

// ---------------- frontier set construction ----------------
__global__ void k_mark_sel() {
    int w    = (blockIdx.x * blockDim.x + threadIdx.x) >> 5;
    int lane = threadIdx.x & 31;
    if (w >= NSEL) return;
    int row = g_nodes[w];
    if (lane == 0) g_flag1[row] = 1;
    int s = g_rowptr[row], e = g_rowptr[row + 1];
    for (int i = s + lane; i < e; i += 32) g_flag1[g_cols[i]] = 1;
}

__global__ void k_compact1() {
    int i = blockIdx.x * blockDim.x + threadIdx.x;
    if (i < N_NODES_ && g_flag1[i]) {
        int p = atomicAdd(&g_n1, 1);
        g_list1[p] = i;
    }
}

__global__ void k_mark_list() {
    int n    = g_n1;
    int w0   = (blockIdx.x * blockDim.x + threadIdx.x) >> 5;
    int lane = threadIdx.x & 31;
    int nw   = (gridDim.x * blockDim.x) >> 5;
    for (int idx = w0; idx < n; idx += nw) {
        int row = g_list1[idx];
        if (lane == 0) g_flag2[row] = 1;
        int s = g_rowptr[row], e = g_rowptr[row + 1];
        for (int i = s + lane; i < e; i += 32) g_flag2[g_cols[i]] = 1;
    }
}

__global__ void k_compact2() {
    int i = blockIdx.x * blockDim.x + threadIdx.x;
    if (i < N_NODES_ && g_flag2[i]) {
        int p = atomicAdd(&g_n2, 1);
        g_list2[p] = i;
    }
}

// ---------------- SpMM over a row list (node-indexed output) ----------------
__global__ void k_spmm_l(int which) {
    int n           = which ? g_n1 : g_n2;
    const int* list = which ? g_list1 : g_list2;
    int gw   = (blockIdx.x * blockDim.x + threadIdx.x) >> 5;
    int lane = threadIdx.x & 31;
    int nw   = (gridDim.x * blockDim.x) >> 5;
    const float4* E4 = (const float4*)g_E;
    float4*       L4 = (float4*)g_LE;
    for (int idx = gw; idx < n; idx += nw) {
        int row = list[idx];
        int s = g_rowptr[row], e = g_rowptr[row + 1];
        if (lane < EMBV) {
            float4 acc = make_float4(0.f, 0.f, 0.f, 0.f);
            for (int i = s; i < e; i++) {
                float v = g_vals[i];
                int   c = g_cols[i];
                float4 x = __ldg(&E4[(size_t)c * EMBV + lane]);
                acc.x = fmaf(v, x.x, acc.x);
                acc.y = fmaf(v, x.y, acc.y);
                acc.z = fmaf(v, x.z, acc.z);
                acc.w = fmaf(v, x.w, acc.w);
            }
            L4[(size_t)row * EMBV + lane] = acc;
        }
    }
}

__global__ void k_spmm_sel() {
    int gw   = (blockIdx.x * blockDim.x + threadIdx.x) >> 5;
    int lane = threadIdx.x & 31;
    if (gw >= NSEL) return;
    int row = g_nodes[gw];
    const float4* E4 = (const float4*)g_E;
    float4*       L4 = (float4*)g_LEsel;
    int s = g_rowptr[row], e = g_rowptr[row + 1];
    if (lane < EMBV) {
        float4 acc = make_float4(0.f, 0.f, 0.f, 0.f);
        for (int i = s; i < e; i++) {
            float v = g_vals[i];
            int   c = g_cols[i];
            float4 x = __ldg(&E4[(size_t)c * EMBV + lane]);
            acc.x = fmaf(v, x.x, acc.x);
            acc.y = fmaf(v, x.y, acc.y);
            acc.z = fmaf(v, x.z, acc.z);
            acc.w = fmaf(v, x.w, acc.w);
        }
        L4[(size_t)gw * EMBV + lane] = acc;
    }
}

// ---------------- tensor-core list GEMM (3xTF32 via mma.sync) ----------------
// Block: 256 threads = 8 warps; tile 64 rows x 80 cols; K = 160.
// Warp w: mi = w&3 (16-row tile), ni = w>>2 (40-col half).
#define GBM 64
#define TCT 256
#define XS  164   // padded Xs row stride (floats), conflict-free

__global__ __launch_bounds__(TCT) void k_gemm_tc(int which, int layer,
                                                 const float* __restrict__ b1l,
                                                 const float* __restrict__ b2l) {
    __shared__ float Xs[GBM * XS];   // 41.98 KB
    __shared__ float Bs[EMB];

    int n           = which ? g_n1 : g_n2;
    const int* list = which ? g_list1 : g_list2;
    int tid  = threadIdx.x;
    int row0 = blockIdx.x * GBM;
    if (row0 >= n) return;

    if (tid < EMB) Bs[tid] = 2.0f * b1l[tid] + b2l[tid];

    // stage X = [LE+E | LE*E] (zeros for OOB entries)
    const float4* E4 = (const float4*)g_E;
    const float4* L4 = (const float4*)g_LE;
    for (int j = tid; j < GBM * EMBV; j += TCT) {
        int r = j / EMBV, c = j % EMBV;
        int idx = row0 + r;
        float4 le = make_float4(0.f, 0.f, 0.f, 0.f), e = le;
        if (idx < n) {
            int node = list[idx];
            le = L4[(size_t)node * EMBV + c];
            e  = E4[(size_t)node * EMBV + c];
        }
        float4* xr = (float4*)(Xs + r * XS);
        xr[c]        = make_float4(le.x + e.x, le.y + e.y, le.z + e.z, le.w + e.w);
        xr[EMBV + c] = make_float4(le.x * e.x, le.y * e.y, le.z * e.z, le.w * e.w);
    }
    __syncthreads();

    int warp = tid >> 5;
    int lane = tid & 31;
    int mi = warp & 3;          // 16-row tile
    int ni = warp >> 2;         // 40-col half
    int g   = lane >> 2;        // 0..7
    int tig = lane & 3;         // 0..3

    float c[5][4];
    #pragma unroll
    for (int t = 0; t < 5; t++)
        #pragma unroll
        for (int j = 0; j < 4; j++) c[t][j] = 0.f;

    const float2* Wp = g_Whl + (size_t)layer * 160 * EMB;
    const float* xr0 = Xs + (mi * 16 + g) * XS;        // row g
    const float* xr1 = xr0 + 8 * XS;                   // row g+8

    #pragma unroll 4
    for (int k0 = 0; k0 < 160; k0 += 8) {
        // A fragments (row-major 16x8): split into hi/lo tf32
        float x0 = xr0[k0 + tig];
        float x1 = xr1[k0 + tig];
        float x2 = xr0[k0 + tig + 4];
        float x3 = xr1[k0 + tig + 4];
        unsigned ah0 = tf32_of(x0), ah1 = tf32_of(x1), ah2 = tf32_of(x2), ah3 = tf32_of(x3);
        unsigned al0 = tf32_of(x0 - __uint_as_float(ah0));
        unsigned al1 = tf32_of(x1 - __uint_as_float(ah1));
        unsigned al2 = tf32_of(x2 - __uint_as_float(ah2));
        unsigned al3 = tf32_of(x3 - __uint_as_float(ah3));

        #pragma unroll
        for (int t = 0; t < 5; t++) {
            int ncol = ni * 40 + t * 8 + g;
            float2 p0 = __ldg(&Wp[(k0 + tig) * EMB + ncol]);       // b0 (hi,lo)
            float2 p1 = __ldg(&Wp[(k0 + tig + 4) * EMB + ncol]);   // b1 (hi,lo)
            unsigned bh0 = __float_as_uint(p0.x), bl0 = __float_as_uint(p0.y);
            unsigned bh1 = __float_as_uint(p1.x), bl1 = __float_as_uint(p1.y);
            mma_tf32(c[t], ah0, ah1, ah2, ah3, bh0, bh1);   // xh*wh
            mma_tf32(c[t], ah0, ah1, ah2, ah3, bl0, bl1);   // xh*wl
            mma_tf32(c[t], al0, al1, al2, al3, bh0, bh1);   // xl*wh
        }
    }

    // epilogue: bias + leaky, scatter to g_E rows
    int gr0 = row0 + mi * 16 + g;       // local rows g / g+8
    int gr1 = gr0 + 8;
    #pragma unroll
    for (int t = 0; t < 5; t++) {
        int col = ni * 40 + t * 8 + 2 * tig;
        float2 b = *(const float2*)&Bs[col];
        float v0 = c[t][0] + b.x, v1 = c[t][1] + b.y;
        float v2 = c[t][2] + b.x, v3 = c[t][3] + b.y;
        v0 = (v0 > 0.f) ? v0 : 0.2f * v0;
        v1 = (v1 > 0.f) ? v1 : 0.2f * v1;
        v2 = (v2 > 0.f) ? v2 : 0.2f * v2;
        v3 = (v3 > 0.f) ? v3 : 0.2f * v3;
        if (gr0 < n) {
            int node = list[gr0];
            *(float2*)(g_E + (size_t)node * EMB + col) = make_float2(v0, v1);
        }
        if (gr1 < n) {
            int node = list[gr1];
            *(float2*)(g_E + (size_t)node * EMB + col) = make_float2(v2, v3);
        }
    }
}

// ---------------- selective GEMM (final layer, proven scalar core) ----------------
#define GT 160

__device__ __forceinline__ void fma4(float4& a, float s, const float4 w) {
    a.x = fmaf(s, w.x, a.x);
    a.y = fmaf(s, w.y, a.y);
    a.z = fmaf(s, w.z, a.z);
    a.w = fmaf(s, w.w, a.w);
}

__global__ __launch_bounds__(GT) void k_gemm_sel(const float* __restrict__ W1l,
                                                 const float* __restrict__ b1l,
                                                 const float* __restrict__ W2l,
                                                 const float* __restrict__ b2l) {
    __shared__ float Xs[GBM * XS];
    __shared__ float Bs[EMB];

    int tid  = threadIdx.x;
    int row0 = blockIdx.x * GBM;   // NSEL = 192*64 exact

    if (tid < EMB) Bs[tid] = 2.0f * b1l[tid] + b2l[tid];

    const float4* E4 = (const float4*)g_E;
    const float4* L4 = (const float4*)g_LEsel;
    for (int j = tid; j < GBM * EMBV; j += GT) {
        int r = j / EMBV, c = j % EMBV;
        int entry = row0 + r;
        int node  = g_nodes[entry];
        float4 le = L4[(size_t)entry * EMBV + c];
        float4 e  = E4[(size_t)node  * EMBV + c];
        float4* xr = (float4*)(Xs + r * XS);
        xr[c]        = make_float4(le.x + e.x, le.y + e.y, le.z + e.z, le.w + e.w);
        xr[EMBV + c] = make_float4(le.x * e.x, le.y * e.y, le.z * e.z, le.w * e.w);
    }
    __syncthreads();

    int tx = tid % EMBV;
    int ty = tid / EMBV;

    float4 acc[8];
    #pragma unroll
    for (int r = 0; r < 8; r++) acc[r] = make_float4(0.f, 0.f, 0.f, 0.f);

    const float4* W14 = (const float4*)W1l;
    const float4* W24 = (const float4*)W2l;
    const float*  xb  = Xs + (ty * 8) * XS;

    for (int k = 0; k < EMB; k += 4) {
        float4 w0 = __ldg(&W14[(k + 0) * EMBV + tx]);
        float4 w1 = __ldg(&W14[(k + 1) * EMBV + tx]);
        float4 w2 = __ldg(&W14[(k + 2) * EMBV + tx]);
        float4 w3 = __ldg(&W14[(k + 3) * EMBV + tx]);
        #pragma unroll
        for (int r = 0; r < 8; r++) {
            float4 xv = *(const float4*)(xb + r * XS + k);
            fma4(acc[r], xv.x, w0);
            fma4(acc[r], xv.y, w1);
            fma4(acc[r], xv.z, w2);
            fma4(acc[r], xv.w, w3);
        }
    }
    for (int k = 0; k < EMB; k += 4) {
        float4 w0 = __ldg(&W24[(k + 0) * EMBV + tx]);
        float4 w1 = __ldg(&W24[(k + 1) * EMBV + tx]);
        float4 w2 = __ldg(&W24[(k + 2) * EMBV + tx]);
        float4 w3 = __ldg(&W24[(k + 3) * EMBV + tx]);
        #pragma unroll
        for (int r = 0; r < 8; r++) {
            float4 xv = *(const float4*)(xb + r * XS + EMB + k);
            fma4(acc[r], xv.x, w0);
            fma4(acc[r], xv.y, w1);
            fma4(acc[r], xv.z, w2);
            fma4(acc[r], xv.w, w3);
        }
    }

    float4 b = ((const float4*)Bs)[tx];
    #pragma unroll
    for (int r = 0; r < 8; r++) {
        int gr = row0 + ty * 8 + r;
        float4 v;
        v.x = acc[r].x + b.x;
        v.y = acc[r].y + b.y;
        v.z = acc[r].z + b.z;
        v.w = acc[r].w + b.w;
        v.x = (v.x > 0.f) ? v.x : 0.2f * v.x;
        v.y = (v.y > 0.f) ? v.y : 0.2f * v.y;
        v.z = (v.z > 0.f) ? v.z : 0.2f * v.z;
        v.w = (v.w > 0.f) ? v.w : 0.2f * v.w;
        ((float4*)g_Esel)[(size_t)gr * EMBV + tx] = v;
    }
}

// ---------------- gather + row-normalize selected rows into output ----------------
__global__ void k_gather(const int* __restrict__ u_id, const int* __restrict__ pos,
                         const int* __restrict__ neg, float* __restrict__ out, int layer) {
    int gw   = (blockIdx.x * blockDim.x + threadIdx.x) >> 5;
    int lane = threadIdx.x & 31;
    if (gw >= NSEL) return;
    int node;
    if (gw < BATCH_)          node = u_id[gw];
    else if (gw < 2 * BATCH_) node = N_USER + pos[gw - BATCH_];
    else                      node = N_USER + neg[gw - 2 * BATCH_];

    const float4* E4 = (const float4*)g_E;
    float4 v = make_float4(0.f, 0.f, 0.f, 0.f);
    if (lane < EMBV) v = E4[(size_t)node * EMBV + lane];
    float ss = v.x * v.x + v.y * v.y + v.z * v.z + v.w * v.w;
    #pragma unroll
    for (int o = 16; o; o >>= 1) ss += __shfl_xor_sync(0xffffffffu, ss, o);
    float scale = 1.0f;
    if (layer > 0) scale = 1.0f / fmaxf(sqrtf(ss), 1e-12f);
    if (lane < EMBV) {
        float4 r = make_float4(v.x * scale, v.y * scale, v.z * scale, v.w * scale);
        ((float4*)(out + (size_t)gw * (4 * EMB) + layer * EMB))[lane] = r;
    }
}

__global__ void k_gather_sel(float* __restrict__ out, int layer) {
    int gw   = (blockIdx.x * blockDim.x + threadIdx.x) >> 5;
    int lane = threadIdx.x & 31;
    if (gw >= NSEL) return;
    const float4* E4 = (const float4*)g_Esel;
    float4 v = make_float4(0.f, 0.f, 0.f, 0.f);
    if (lane < EMBV) v = E4[(size_t)gw * EMBV + lane];
    float ss = v.x * v.x + v.y * v.y + v.z * v.z + v.w * v.w;
    #pragma unroll
    for (int o = 16; o; o >>= 1) ss += __shfl_xor_sync(0xffffffffu, ss, o);
    float scale = 1.0f / fmaxf(sqrtf(ss), 1e-12f);
    if (lane < EMBV) {
        float4 r = make_float4(v.x * scale, v.y * scale, v.z * scale, v.w * scale);
        ((float4*)(out + (size_t)gw * (4 * EMB) + layer * EMB))[lane] = r;
    }
}

// ---------------- launch (single stream, proven R12 ordering) ----------------
extern "C" void kernel_launch(void* const* d_in, const int* in_sizes, int n_in,
                              void* d_out, int out_size) {
    const int*   u_id      = (const int*)d_in[0];
    const int*   age       = (const int*)d_in[1];
    const int*   sex       = (const int*)d_in[2];
    const int*   month     = (const int*)d_in[3];
    const int*   day       = (const int*)d_in[4];
    const int*   dow       = (const int*)d_in[5];
    const int*   pos       = (const int*)d_in[6];
    const int*   neg       = (const int*)d_in[7];
    const int*   lrows     = (const int*)d_in[8];
    const int*   lcols     = (const int*)d_in[9];
    const float* lvals     = (const float*)d_in[10];
    const float* user_tab  = (const float*)d_in[11];
    const float* item_tab  = (const float*)d_in[12];
    const float* age_tab   = (const float*)d_in[13];
    const float* sex_tab   = (const float*)d_in[14];
    const float* month_tab = (const float*)d_in[15];
    const float* day_tab   = (const float*)d_in[16];
    const float* dow_tab   = (const float*)d_in[17];
    const float* W1        = (const float*)d_in[18];
    const float* b1        = (const float*)d_in[19];
    const float* W2        = (const float*)d_in[20];
    const float* b2        = (const float*)d_in[21];
    float* out = (float*)d_out;

    const int GMAX = (N_NODES_ + GBM - 1) / GBM;

    // CSR build + W split precompute
    k_init<<<(N_NODES_ + 255) / 256, 256>>>();
    k_wsplit<<<(NLAYER * 160 * EMB + 255) / 256, 256>>>(W1, W2);
    k_hist<<<(NNZ_ + 255) / 256, 256>>>(lrows);
    int nb = (N_NODES_ + 1023) / 1024;
    k_scan1<<<nb, 1024>>>();
    k_scan2<<<1, 1024>>>(nb);
    k_scan3<<<(N_NODES_ + 255) / 256, 256>>>();
    k_scatter<<<(NNZ_ + 255) / 256, 256>>>(lrows, lcols, lvals);

    // E0 + blend + node list
    k_init_E<<<(N_NODES_ * EMBV + 255) / 256, 256>>>((const float4*)user_tab,
                                                     (const float4*)item_tab);
    k_winner<<<(BATCH_ + 255) / 256, 256>>>(u_id);
    k_blend<<<(BATCH_ + 255) / 256, 256>>>(u_id, age, sex, month, day, dow, user_tab,
                                           age_tab, sex_tab, month_tab, day_tab, dow_tab);
    k_nodes<<<(NSEL + 255) / 256, 256>>>(u_id, pos, neg);

    // frontier sets: S1 = Ssel ∪ N(Ssel); S2 = S1 ∪ N(S1)
    k_mark_sel<<<(NSEL * 32 + 255) / 256, 256>>>();
    k_compact1<<<(N_NODES_ + 255) / 256, 256>>>();
    k_mark_list<<<1024, 256>>>();
    k_compact2<<<(N_NODES_ + 255) / 256, 256>>>();

    // layer-0 slice (unnormalized E0)
    k_gather<<<(NSEL * 32 + 255) / 256, 256>>>(u_id, pos, neg, out, 0);

    // layer 0 over S2 (tensor-core GEMM)
    k_spmm_l<<<2048, 256>>>(0);
    k_gemm_tc<<<GMAX, TCT>>>(0, 0, b1, b2);
    k_gather<<<(NSEL * 32 + 255) / 256, 256>>>(u_id, pos, neg, out, 1);

    // layer 1 over S1 (tensor-core GEMM)
    k_spmm_l<<<2048, 256>>>(1);
    k_gemm_tc<<<GMAX, TCT>>>(1, 1, b1 + EMB, b2 + EMB);
    k_gather<<<(NSEL * 32 + 255) / 256, 256>>>(u_id, pos, neg, out, 2);

    // layer 2: selective (entry-indexed, proven scalar core)
    k_spmm_sel<<<(NSEL * 32 + 255) / 256, 256>>>();
    k_gemm_sel<<<NSEL / GBM, GT>>>(W1 + (size_t)2 * EMB * EMB, b1 + 2 * EMB,
                                   W2 + (size_t)2 * EMB * EMB, b2 + 2 * EMB);
    k_gather_sel<<<(NSEL * 32 + 255) / 256, 256>>>(out, NLAYER);
}